// round 17
// baseline (speedup 1.0000x reference)
#include <cuda_runtime.h>
#include <cooperative_groups.h>
#include <cstdint>

namespace cg = cooperative_groups;

// Problem constants
#define T_DIM 1024
#define N_DIM 32
#define CI    512
#define CO    512

// Decomposition
#define CSIZE   4              // CTAs per cluster (one cluster per batch)
#define PSLICE  128            // neurons per CTA
#define ROWS_S  384            // RT rows cached in smem (12 mask words)
#define SCANTHR 512            // scan threads: 4 slots x 128 cols
#define GEMMTHR 256            // gemm threads: 8 warps
#define NTHR    (SCANTHR + GEMMTHR)   // 768
#define SLOTW   112
#define GLOTW   32
#define KBUDGET 9              // gemm k-iters per scan step (margin vs 8)

// GEMM tile geometry (per CTA: 2 o-tiles of 64, t-tiles of 128, BK=16)
#define GBK 16
#define WSW 68                 // padded ws row

// Scratch (allocation-free rule: __device__ globals).
__device__ float g_z[T_DIM * N_DIM * CO];   // [t][n][o]
__device__ float g_RT[(CO + 1) * CO];       // RT[o][p] = R[p][o]; row CO = 0

// ---------------------------------------------------------------------------
// Kernel 1: transpose R -> RT (plus zero sentinel row CO).
// ---------------------------------------------------------------------------
__global__ void transpose_R_kernel(const float* __restrict__ R) {
    int idx = blockIdx.x * blockDim.x + threadIdx.x;
    if (idx >= (CO + 1) * CO) return;
    int o = idx >> 9;
    int p = idx & 511;
    g_RT[idx] = (o < CO) ? R[p * CO + o] : 0.f;
}

// ---------------------------------------------------------------------------
// Fused kernel: warps 0..15 run the R9 LIF scan; warps 16..23 compute this
// cluster's z tiles in lockstep (KBUDGET k-iters between cluster.syncs).
// smem layout (16B aligned throughout):
//   xs[16][128] | ws[16][68] | RTs[385][128] | stage[128][17] | comb[3][128]
//   | masks[2][16] | lists_s[4][112] | lists_g[4][32] | tail[8]
// ---------------------------------------------------------------------------
#define XS_ELEMS   (GBK * 128)
#define WS_ELEMS   (GBK * WSW)
#define RTS_ELEMS  ((ROWS_S + 1) * PSLICE)
#define STAGE_ELEMS (PSLICE * 17)
#define SMEM_BYTES ((XS_ELEMS + WS_ELEMS + RTS_ELEMS + STAGE_ELEMS \
                     + 3 * PSLICE) * 4 + 2 * 16 * 4 \
                     + 4 * SLOTW * 4 + 4 * GLOTW * 4 + 8 * 2)

#define BAR_GEMM() asm volatile("bar.sync 1, 256;" ::: "memory")
#define BAR_SCAN() asm volatile("bar.sync 2, 512;" ::: "memory")

extern __shared__ float smem_dyn[];

__device__ __forceinline__ void gemm_load_slab(
    float* xs, float* ws, const float* __restrict__ x,
    const float* __restrict__ W, int n, int t0, int o0, int c0, int gtid)
{
    const float* xbase = x + (size_t)n * CI * T_DIM + t0;
#pragma unroll
    for (int it = 0; it < 8; ++it) {
        int idx = gtid + it * 256;
        int cc = idx >> 7, tt = idx & 127;
        xs[cc * 128 + tt] = xbase[(c0 + cc) * T_DIM + tt];
    }
#pragma unroll
    for (int it = 0; it < 4; ++it) {
        int idx = gtid + it * 256;
        int oo = idx >> 4, cc = idx & 15;
        ws[cc * WSW + oo] = W[(o0 + oo) * CI + c0 + cc];
    }
}

// k-iters [kpos, kpos+take) of the current slab; R9 numerics per output.
__device__ __forceinline__ void gemm_consume(
    const float* xs, const float* ws, int kpos, int take,
    int ty, int tx, float acc[8][4])
{
    for (int k = kpos; k < kpos + take; ++k) {
        float a[8], b[4];
#pragma unroll
        for (int i = 0; i < 8; ++i) a[i] = xs[k * 128 + ty * 8 + i];
#pragma unroll
        for (int j = 0; j < 4; ++j) b[j] = ws[k * WSW + tx * 4 + j];
#pragma unroll
        for (int i = 0; i < 8; ++i)
#pragma unroll
            for (int j = 0; j < 4; ++j)
                acc[i][j] += a[i] * b[j];
    }
}

__device__ __forceinline__ void gemm_write_z(
    int t0, int n, int o0, int ty, int tx, float acc[8][4])
{
#pragma unroll
    for (int i = 0; i < 8; ++i) {
        int t = t0 + ty * 8 + i;
        float4 v4 = make_float4(acc[i][0], acc[i][1], acc[i][2], acc[i][3]);
        *(float4*)&g_z[((size_t)t * N_DIM + n) * CO + o0 + tx * 4] = v4;
    }
}

__global__ void __cluster_dims__(CSIZE, 1, 1) __launch_bounds__(NTHR, 1)
fused_kernel(float* __restrict__ out, const float* __restrict__ x,
             const float* __restrict__ W)
{
    float*    xs      = smem_dyn;                    // [16][128]
    float*    ws      = xs + XS_ELEMS;               // [16][68]
    float*    RTs     = ws + WS_ELEMS;               // [385][128]
    float*    stage   = RTs + RTS_ELEMS;             // [128][17]
    float*    comb    = stage + STAGE_ELEMS;         // [3][128]
    unsigned* masks   = (unsigned*)(comb + 3 * PSLICE);   // [2][16]
    int*      lists_s = (int*)(masks + 32);          // [4][SLOTW]
    int*      lists_g = lists_s + 4 * SLOTW;         // [4][GLOTW]
    short*    tail    = (short*)(lists_g + 4 * GLOTW);    // [8]

    cg::cluster_group cluster = cg::this_cluster();
    const int rank = (int)cluster.block_rank();
    const int n    = blockIdx.x / CSIZE;

    const int tid     = threadIdx.x;
    const bool is_scan = (tid < SCANTHR);

    // ---- scan-role ids ----
    const int warp = tid >> 5;
    const int lane = tid & 31;
    const int slot = (tid >> 7) & 3;
    const int col  = tid & 127;
    const int p    = rank * PSLICE + col;

    // ---- gemm-role ids + state ----
    const int gtid = tid - SCANTHR;          // 0..255 (valid when !is_scan)
    const int gty  = gtid >> 4;              // 8 t-outputs
    const int gtx  = gtid & 15;              // 4 o-outputs
    float gacc[8][4];
    int gtile = 0, gslab = 0, gkpos = 0;     // continuous tiles 0..13 (= t-tiles 1..7)

    if (is_scan) {
        // RT slice: smem row 0 = zeros, rows 1..384 = g_RT rows 0..383.
        RTs[col] = 0.f;
        for (int o = slot; o < ROWS_S; o += 4)
            RTs[(o + 1) * PSLICE + col] = g_RT[o * CO + p];
        if (slot == 0) stage[col * 17 + 0] = 0.f;   // delay shift
    } else {
        // Bootstrap: t-tile 0 (this CTA's two o-tiles) at full speed.
#pragma unroll
        for (int i = 0; i < 8; ++i)
#pragma unroll
            for (int j = 0; j < 4; ++j) gacc[i][j] = 0.f;
        for (int bt = 0; bt < 2; ++bt) {
            int o0b = ((rank << 1) + bt) * 64;
            for (int sl = 0; sl < 32; ++sl) {
                BAR_GEMM();
                gemm_load_slab(xs, ws, x, W, n, 0, o0b, sl * GBK, gtid);
                BAR_GEMM();
                gemm_consume(xs, ws, 0, GBK, gty, gtx, gacc);
            }
            gemm_write_z(0, n, o0b, gty, gtx, gacc);
#pragma unroll
            for (int i = 0; i < 8; ++i)
#pragma unroll
                for (int j = 0; j < 4; ++j) gacc[i][j] = 0.f;
        }
        // Preload slab 0 of continuous tile 0 (t-tile 1, o-tile rank*2).
        BAR_GEMM();
        gemm_load_slab(xs, ws, x, W, n, 128, (rank << 1) * 64, 0, gtid);
        BAR_GEMM();
    }

    __syncthreads();    // all 768: RT + bootstrap done
    cluster.sync();     // t-tile 0 release; cluster smem visible

    float cur = 0.f, v = 0.f, s = 0.f;

    const float* RTc  = RTs + col;
    const char*  RTb  = (const char*)(RTs + col);
    const float* gcol = g_RT + p;
    const char*  gb   = (const char*)(g_RT + p);

    for (int t = 0; t < T_DIM - 1; ++t) {
        const int par = t & 1;
        float zv = 0.f;

        if (is_scan && slot == 0) {
            zv = g_z[((size_t)t * N_DIM + n) * CO + p];
            unsigned bal = __ballot_sync(0xffffffffu, s > 0.5f);
            if (lane < CSIZE) {
                unsigned* dst = cluster.map_shared_rank(
                    &masks[par * 16 + rank * 4 + warp], (unsigned)lane);
                *dst = bal;
            }
        }
        cluster.sync();   // all 768x4 threads; masks[par] visible; z release

        if (is_scan) {
            // ---- parallel list build (verbatim R9, ROWS_S=384) ----
            const unsigned* mw = masks + par * 16;
            unsigned myw = mw[warp];
            int cw = (lane < 16) ? __popc(mw[lane]) : 0;
            int inc = cw;
#pragma unroll
            for (int d = 1; d < 16; d <<= 1) {
                int u = __shfl_up_sync(0xffffffffu, inc, d);
                if (lane >= d) inc += u;
            }
            const int tot   = __shfl_sync(0xffffffffu, inc, 15);
            const int totS  = __shfl_sync(0xffffffffu, inc, 11);
            const int exc_w = (warp == 0) ? 0
                              : __shfl_sync(0xffffffffu, inc, warp - 1);
            const int M4 = tot & ~3;
            const int S  = (totS < M4) ? totS : M4;

            if ((myw >> lane) & 1u) {
                int rk = exc_w + __popc(myw & ((1u << lane) - 1u));
                if (rk >= M4) {
                    tail[rk - M4] = (short)tid;
                } else if (tid < ROWS_S) {
                    lists_s[(rk & 3) * SLOTW + (rk >> 2)] = (tid + 1) * 512;
                } else {
                    int sl = rk & 3;
                    int cs = (S >> 2) + (((S & 3) > sl) ? 1 : 0);
                    lists_g[sl * GLOTW + (rk >> 2) - cs] = tid * 2048;
                }
            }
            if (tid < 16) {
                int sl = tid >> 2, j = tid & 3;
                int cs = (S >> 2) + (((S & 3) > sl) ? 1 : 0);
                if (cs + j < ((cs + 3) & ~3)) lists_s[sl * SLOTW + cs + j] = 0;
            } else if (tid < 48) {
                int k2 = tid - 16;
                int sl = k2 >> 3, j = k2 & 7;
                int cs = (S >> 2) + (((S & 3) > sl) ? 1 : 0);
                int cg = (M4 >> 2) - cs;
                if (cg + j < ((cg + 7) & ~7))
                    lists_g[sl * GLOTW + cg + j] = CO * 2048;
            }
            BAR_SCAN();

            const int cs_my  = (S >> 2) + (((S & 3) > slot) ? 1 : 0);
            const int nblk_s = ((cs_my + 3) & ~3) >> 2;
            const int cg_my  = (M4 >> 2) - cs_my;
            const int nblk_g = ((cg_my + 7) & ~7) >> 3;   // <= 4

            // gmem prefetch first
            const int* lg = lists_g + slot * GLOTW;
            float G[32];
#pragma unroll
            for (int b = 0; b < 4; ++b) {
                if (b < nblk_g) {
#pragma unroll
                    for (int u = 0; u < 8; ++u) {
                        int e = lg[b * 8 + u];
                        G[b * 8 + u] = __ldg((const float*)(gb + e));
                    }
                } else {
#pragma unroll
                    for (int u = 0; u < 8; ++u) G[b * 8 + u] = 0.f;
                }
            }

            // smem gather (3 instr/row)
            float acc = 0.f;
            const int4* ls4 = (const int4*)(lists_s + slot * SLOTW);
            if (nblk_s > 0) {
                int4 e = ls4[0];
                for (int b = 0; b < nblk_s; ++b) {
                    int4 en = (b + 1 < nblk_s) ? ls4[b + 1] : e;
                    acc += *(const float*)(RTb + e.x);
                    acc += *(const float*)(RTb + e.y);
                    acc += *(const float*)(RTb + e.z);
                    acc += *(const float*)(RTb + e.w);
                    e = en;
                }
            }
#pragma unroll
            for (int u = 0; u < 32; ++u) acc += G[u];

            if (slot == 0 && M4 < tot) {
                int rem = tot - M4;
                int o0 = tail[0];
                float r0 = (o0 < ROWS_S) ? RTc[(o0 + 1) * PSLICE]
                                         : __ldg(&gcol[o0 * CO]);
                float r1 = 0.f, r2 = 0.f;
                if (rem > 1) { int o1 = tail[1];
                    r1 = (o1 < ROWS_S) ? RTc[(o1 + 1) * PSLICE]
                                       : __ldg(&gcol[o1 * CO]); }
                if (rem > 2) { int o2 = tail[2];
                    r2 = (o2 < ROWS_S) ? RTc[(o2 + 1) * PSLICE]
                                       : __ldg(&gcol[o2 * CO]); }
                acc += r0; acc += r1; acc += r2;
            }

            if (slot != 0) comb[(slot - 1) * PSLICE + col] = acc;
            BAR_SCAN();

            if (slot == 0) {
                float a1 = comb[col];
                float a2 = comb[PSLICE + col];
                float a3 = comb[2 * PSLICE + col];
                float rec = zv + ((acc + a1) + (a2 + a3));

                cur = 0.75f * cur + rec;
                v   = 0.9f * v * (1.f - s) + cur;
                float s_new = (v >= 1.0f) ? 1.f : 0.f;
                s = s_new;

                stage[col * 17 + ((t + 1) & 15)] = s_new;
            }

            if (((t + 1) & 15) == 15) {
                BAR_SCAN();
                const int qbase = (t + 1) & ~15;
#pragma unroll
                for (int it = 0; it < 4; ++it) {
                    int vidx = it * SCANTHR + tid;
                    int pp = vidx >> 4;
                    int tt = vidx & 15;
                    out[((size_t)n * CO + rank * PSLICE + pp) * T_DIM
                        + qbase + tt] = stage[pp * 17 + tt];
                }
            }
            // reuse of masks/lists/stage guarded by next cluster.sync
        } else {
            // ---- GEMM chunk: up to KBUDGET k-iters, deterministic ----
            int budget = KBUDGET;
            while (budget > 0 && gtile < 14) {
                int take = 16 - gkpos;
                if (take > budget) take = budget;
                gemm_consume(xs, ws, gkpos, take, gty, gtx, gacc);
                gkpos += take; budget -= take;
                if (gkpos == 16) {
                    gkpos = 0;
                    ++gslab;
                    int t0c = (1 + (gtile >> 1)) * 128;
                    int o0c = ((rank << 1) + (gtile & 1)) * 64;
                    if (gslab == 32) {
                        gemm_write_z(t0c, n, o0c, gty, gtx, gacc);
#pragma unroll
                        for (int i = 0; i < 8; ++i)
#pragma unroll
                            for (int j = 0; j < 4; ++j) gacc[i][j] = 0.f;
                        gslab = 0;
                        ++gtile;
                        if (gtile == 14) break;
                        t0c = (1 + (gtile >> 1)) * 128;
                        o0c = ((rank << 1) + (gtile & 1)) * 64;
                    }
                    BAR_GEMM();
                    gemm_load_slab(xs, ws, x, W, n, t0c, o0c,
                                   gslab * GBK, gtid);
                    BAR_GEMM();
                }
            }
        }
    }
}

// ---------------------------------------------------------------------------
// Launch: two kernels, one stream, no events. Graph-trivial.
// ---------------------------------------------------------------------------
extern "C" void kernel_launch(void* const* d_in, const int* in_sizes, int n_in,
                              void* d_out, int out_size)
{
    const float* x = (const float*)d_in[0];   // [32, 512, 1024]
    const float* W = (const float*)d_in[1];   // [512, 512]
    const float* R = (const float*)d_in[2];   // [512, 512]
    float* out = (float*)d_out;               // [32, 512, 1024]

    cudaFuncSetAttribute(fused_kernel,
                         cudaFuncAttributeMaxDynamicSharedMemorySize,
                         SMEM_BYTES);

    transpose_R_kernel<<<((CO + 1) * CO + 255) / 256, 256>>>(R);
    fused_kernel<<<N_DIM * CSIZE, NTHR, SMEM_BYTES>>>(out, x, W);
}